// round 15
// baseline (speedup 1.0000x reference)
#include <cuda_runtime.h>
#include <cuda_bf16.h>
#include <cstdint>

// Problem constants (fixed by reference):
//   g: (32, 16, 2048, 3) fp32, ar_phi: (3,3), ar_eta: (3,), ar_c: (3,)
//   P=3, KMAX=5 (11 windings), output: (32,) fp32
#define N_MC      32
#define N_SAMP    16
#define T_LEN     2048
#define TPRIME    2044                   // T - 1 - P
#define ROW_ELEMS (T_LEN * 3)            // 6144 floats
#define ROW_VEC4  (ROW_ELEMS / 4)        // 1536 float4s per row

#define CLUSTER   8                      // CTAs per cluster = per output m
#define SPC       2                      // samples per CTA (8*2 = 16 = N_SAMP)
#define GRID      (N_MC * CLUSTER)       // 256 CTAs, single wave
#define BLOCK     256
#define CHUNK     8                      // t-outputs per thread per sample

#define PI_F      3.14159265358979323846f
#define TWO_PI_F  6.28318530717958647693f
#define INV_2PI_F 0.15915494309189533577f
#define MAGIC_F   12582912.0f            // 1.5 * 2^23

// ---- Packed f32x2 helpers (Blackwell FFMA2 path; ptxas won't auto-fuse).
typedef unsigned long long u64;
__device__ __forceinline__ u64 pack2(float lo, float hi) {
    u64 r; asm("mov.b64 %0, {%1, %2};" : "=l"(r) : "f"(lo), "f"(hi)); return r;
}
__device__ __forceinline__ void unpack2(u64 v, float& lo, float& hi) {
    asm("mov.b64 {%0, %1}, %2;" : "=f"(lo), "=f"(hi) : "l"(v));
}
#define FMA2(d, a, b, c) \
    asm("fma.rn.f32x2 %0, %1, %2, %3;" : "=l"(d) : "l"(a), "l"(b), "l"(c))
#define ADD2(d, a, b) \
    asm("add.rn.f32x2 %0, %1, %2;" : "=l"(d) : "l"(a), "l"(b))

// Scalar torus logmap (dim 2): x - 2*pi*rint(x/2pi). Matches mod(x+pi,2pi)-pi
// except exact half-period boundaries (measure zero in fp32 data).
__device__ __forceinline__ float wrapf(float x) {
    return fmaf(-rintf(x * INV_2PI_F), TWO_PI_F, x);
}

__device__ __forceinline__ uint32_t smem_u32(const void* p) {
    uint32_t a;
    asm("{ .reg .u64 t; cvta.to.shared.u64 t, %1; cvt.u32.u64 %0, t; }"
        : "=r"(a) : "l"(p));
    return a;
}

__global__ __launch_bounds__(BLOCK) __cluster_dims__(CLUSTER, 1, 1)
void arp_cluster_kernel(const float* __restrict__ g,
                        const float* __restrict__ ar_phi,
                        const float* __restrict__ ar_eta,
                        const float* __restrict__ ar_c,
                        float* __restrict__ out) {
    __shared__ float sred[3][BLOCK / 32];
    __shared__ float slots[CLUSTER][3];   // leader CTA collects per-rank sums

    const int tid = threadIdx.x;
    const int m   = blockIdx.x / CLUSTER;
    uint32_t rank;
    asm("mov.u32 %0, %%cluster_ctarank;" : "=r"(rank));

    // Small params (L1-cached broadcast loads).
    float ph[3][3], cc[3];
#pragma unroll
    for (int d = 0; d < 3; d++) {
        ph[d][0] = __ldg(&ar_phi[d * 3 + 0]);
        ph[d][1] = __ldg(&ar_phi[d * 3 + 1]);
        ph[d][2] = __ldg(&ar_phi[d * 3 + 2]);
        cc[d]    = __ldg(&ar_c[d]);
    }

    // Packed constants for dims {0,1}.
    const u64 inv2pi2   = pack2(INV_2PI_F, INV_2PI_F);
    const u64 magic2    = pack2(MAGIC_F, MAGIC_F);
    const u64 negmagic2 = pack2(-MAGIC_F, -MAGIC_F);
    const u64 neg2pi2   = pack2(-TWO_PI_F, -TWO_PI_F);
    const u64 negone2   = pack2(-1.0f, -1.0f);
    const u64 negcc2    = pack2(-cc[0], -cc[1]);
    u64 negph2[3];
#pragma unroll
    for (int k = 0; k < 3; k++) negph2[k] = pack2(-ph[0][k], -ph[1][k]);

    const int t0   = tid * CHUNK;
    const int base = (3 * t0) >> 2;       // 3*t0 divisible by 4 (t0 % 8 == 0)
    const int row0 = m * N_SAMP + (int)rank * SPC;

    // ---- SINGLE front-batched memory exposure: BOTH sample-rows' 9 float4s
    // issued back-to-back (18 independent LDG.128 in flight per thread)
    // before any compute consumes them.
    const float4* g4a = reinterpret_cast<const float4*>(g)
                      + (size_t)row0 * ROW_VEC4;
    const float4* g4b = g4a + ROW_VEC4;
    float f0[36], f1[36];
#pragma unroll
    for (int k = 0; k < 9; k++) {
        int idx = base + k;
        if (idx > ROW_VEC4 - 1) idx = ROW_VEC4 - 1;   // tail clamp (unused data)
        float4 va = __ldg(&g4a[idx]);
        f0[4 * k + 0] = va.x; f0[4 * k + 1] = va.y;
        f0[4 * k + 2] = va.z; f0[4 * k + 3] = va.w;
    }
#pragma unroll
    for (int k = 0; k < 9; k++) {
        int idx = base + k;
        if (idx > ROW_VEC4 - 1) idx = ROW_VEC4 - 1;
        float4 vb = __ldg(&g4b[idx]);
        f1[4 * k + 0] = vb.x; f1[4 * k + 1] = vb.y;
        f1[4 * k + 2] = vb.z; f1[4 * k + 3] = vb.w;
    }

    // ---- AR(3) on wrapped first-diffs. Dims {0,1} run in f32x2 lanes
    // (adjacent in the t-major triplets); dim 2 scalar. Each dx once.
    u64   accp   = pack2(0.f, 0.f);      // packed acc for dims 0,1
    float acc2   = 0.f;                  // scalar acc for dim 2
#pragma unroll
    for (int s = 0; s < SPC; s++) {
        const float* f = (s == 0) ? f0 : f1;

        // Packed dx for dims {0,1}: diff via FMA2(a_j, -1, a_{j+1}),
        // wrap via magic-number round (FMA2 + ADD2 + FMA2). IEEE-rn lanes,
        // bit-identical to the scalar ops they replace.
        u64 dxp[CHUNK + 3];
#pragma unroll
        for (int j = 0; j < CHUNK + 3; j++) {
            u64 aj  = pack2(f[3 * j + 0],       f[3 * j + 1]);
            u64 aj1 = pack2(f[3 * (j + 1) + 0], f[3 * (j + 1) + 1]);
            u64 dif, y, kk;
            FMA2(dif, aj, negone2, aj1);          // a_{j+1} - a_j
            FMA2(y, dif, inv2pi2, magic2);
            ADD2(kk, y, negmagic2);               // rint(dif/2pi)
            FMA2(dxp[j], kk, neg2pi2, dif);       // dif - 2pi*k
        }
        // Scalar dx for dim 2.
        float dx2[CHUNK + 3];
#pragma unroll
        for (int j = 0; j < CHUNK + 3; j++)
            dx2[j] = wrapf(f[3 * (j + 1) + 2] - f[3 * j + 2]);

#pragma unroll
        for (int j = 0; j < CHUNK; j++) {
            const bool ok = (t0 + j < TPRIME);    // false only in tid 255 tail
            // Packed dims 0,1.
            u64 v, u2;
            FMA2(v, negph2[0], dxp[j + 2], dxp[j + 3]);
            FMA2(v, negph2[1], dxp[j + 1], v);
            FMA2(v, negph2[2], dxp[j],     v);
            ADD2(u2, v, negcc2);
            if (!ok) u2 = pack2(0.f, 0.f);
            FMA2(accp, u2, u2, accp);
            // Scalar dim 2.
            float dyv = dx2[j + 3] - (ph[2][0] * dx2[j + 2]
                                    + ph[2][1] * dx2[j + 1]
                                    + ph[2][2] * dx2[j]);
            float u = dyv - cc[2];
            if (ok) acc2 = fmaf(u, u, acc2);
        }
    }

    float acc[3];
    unpack2(accp, acc[0], acc[1]);
    acc[2] = acc2;

    // ---- Warp reduce, then 8-warp fold.
#pragma unroll
    for (int off = 16; off; off >>= 1)
#pragma unroll
        for (int d = 0; d < 3; d++)
            acc[d] += __shfl_xor_sync(0xffffffffu, acc[d], off);

    const int lane = tid & 31;
    const int warp = tid >> 5;
    if (lane == 0)
#pragma unroll
        for (int d = 0; d < 3; d++) sred[d][warp] = acc[d];
    __syncthreads();

    // ---- tid0 pushes this CTA's 3 sums into the LEADER CTA's slots via DSMEM.
    if (tid == 0) {
        float S[3];
#pragma unroll
        for (int d = 0; d < 3; d++) {
            float v = sred[d][0];
#pragma unroll
            for (int w = 1; w < BLOCK / 32; w++) v += sred[d][w];
            S[d] = v;
        }
        uint32_t laddr = smem_u32(&slots[rank][0]);   // same layout in every CTA
        uint32_t raddr;
        asm volatile("mapa.shared::cluster.u32 %0, %1, %2;"
                     : "=r"(raddr) : "r"(laddr), "r"(0u));   // -> leader (rank 0)
#pragma unroll
        for (int d = 0; d < 3; d++)
            asm volatile("st.shared::cluster.f32 [%0], %1;"
                         :: "r"(raddr + 4u * d), "f"(S[d]) : "memory");
    }

    // Cluster barrier: release DSMEM stores, then leader may read.
    asm volatile("barrier.cluster.arrive.aligned;" ::: "memory");
    asm volatile("barrier.cluster.wait.aligned;" ::: "memory");

    // ---- Leader CTA: fold 8 ranks + closed-form winding constant, write out[m].
    //   sum_{k=-5..5} winding log-density collapses (sum k = 0, sum k^2 = 110)
    //   per (t,d) to: -5.5*u^2/var - 220*pi^2/var - 11*log(e) - 5.5*log(2*pi).
    // fp32 throughout: abs error ~1e4 vs tolerance budget ~8.5e7.
    if (rank == 0 && tid == 0) {
        float res = 0.f;
#pragma unroll
        for (int d = 0; d < 3; d++) {
            float Sd = 0.f;
#pragma unroll
            for (int r = 0; r < CLUSTER; r++) Sd += slots[r][d];
            float e   = fabsf(ar_eta[d]);            // scale = sqrt(eta^2)
            float var = e * e;
            float C = -220.f * (PI_F * PI_F) / var - 11.f * logf(e)
                      - 5.5f * logf(TWO_PI_F);
            res += -5.5f * Sd / var + (float)(N_SAMP * TPRIME) * C;
        }
        out[m] = res;
    }
}

extern "C" void kernel_launch(void* const* d_in, const int* in_sizes, int n_in,
                              void* d_out, int out_size) {
    const float* g      = (const float*)d_in[0];
    const float* ar_phi = (const float*)d_in[1];
    const float* ar_eta = (const float*)d_in[2];
    const float* ar_c   = (const float*)d_in[3];
    float* out = (float*)d_out;

    arp_cluster_kernel<<<GRID, BLOCK>>>(g, ar_phi, ar_eta, ar_c, out);
}

// round 16
// speedup vs baseline: 1.0294x; 1.0294x over previous
#include <cuda_runtime.h>
#include <cuda_bf16.h>
#include <cstdint>

// Problem constants (fixed by reference):
//   g: (32, 16, 2048, 3) fp32, ar_phi: (3,3), ar_eta: (3,), ar_c: (3,)
//   P=3, KMAX=5 (11 windings), output: (32,) fp32
#define N_MC      32
#define N_SAMP    16
#define T_LEN     2048
#define TPRIME    2044                   // T - 1 - P
#define ROW_ELEMS (T_LEN * 3)            // 6144 floats
#define ROW_VEC4  (ROW_ELEMS / 4)        // 1536 float4s per row

#define CLUSTER   4                      // CTAs per cluster = per output m
#define SPC       4                      // samples per CTA (4*4 = 16 = N_SAMP)
#define GRID      (N_MC * CLUSTER)       // 128 CTAs -> ~1 CTA/SM (oe = 1)
#define BLOCK     512                    // 2 groups x 256 thr; each group: 2 rows
#define CHUNK     8                      // t-outputs per thread per sample
#define NWARPS    (BLOCK / 32)           // 16

#define PI_F      3.14159265358979323846f
#define TWO_PI_F  6.28318530717958647693f
#define INV_2PI_F 0.15915494309189533577f

// Torus logmap: x - 2*pi*rint(x/2pi). Matches mod(x+pi,2pi)-pi except exact
// half-period boundaries (measure zero in fp32 data).
__device__ __forceinline__ float wrapf(float x) {
    return fmaf(-rintf(x * INV_2PI_F), TWO_PI_F, x);
}

__device__ __forceinline__ uint32_t smem_u32(const void* p) {
    uint32_t a;
    asm("{ .reg .u64 t; cvta.to.shared.u64 t, %1; cvt.u32.u64 %0, t; }"
        : "=r"(a) : "l"(p));
    return a;
}

__global__ __launch_bounds__(BLOCK) __cluster_dims__(CLUSTER, 1, 1)
void arp_cluster_kernel(const float* __restrict__ g,
                        const float* __restrict__ ar_phi,
                        const float* __restrict__ ar_eta,
                        const float* __restrict__ ar_c,
                        float* __restrict__ out) {
    __shared__ float sred[3][NWARPS];
    __shared__ float slots[CLUSTER][3];   // leader CTA collects per-rank sums

    const int tid   = threadIdx.x;
    const int inner = tid & 255;          // position within sample-group
    const int sid   = tid >> 8;           // group 0 or 1 (2 rows each)
    const int m     = blockIdx.x / CLUSTER;
    uint32_t rank;
    asm("mov.u32 %0, %%cluster_ctarank;" : "=r"(rank));

    // Small params (L1-cached broadcast loads).
    float ph[3][3], cc[3];
#pragma unroll
    for (int d = 0; d < 3; d++) {
        ph[d][0] = __ldg(&ar_phi[d * 3 + 0]);
        ph[d][1] = __ldg(&ar_phi[d * 3 + 1]);
        ph[d][2] = __ldg(&ar_phi[d * 3 + 2]);
        cc[d]    = __ldg(&ar_c[d]);
    }

    const int t0   = inner * CHUNK;
    const int base = (3 * t0) >> 2;       // 3*t0 divisible by 4 (t0 % 8 == 0)
    // This group's 2 consecutive rows (CTA covers 4: rank*4 + sid*2 + {0,1}).
    const int row0 = m * N_SAMP + (int)rank * SPC + sid * 2;

    // ---- SINGLE front-batched memory exposure: BOTH of this group's rows
    // (18 independent LDG.128 per thread) before any compute consumes them.
    const float4* g4a = reinterpret_cast<const float4*>(g)
                      + (size_t)row0 * ROW_VEC4;
    const float4* g4b = g4a + ROW_VEC4;
    float f0[36], f1[36];
#pragma unroll
    for (int k = 0; k < 9; k++) {
        int idx = base + k;
        if (idx > ROW_VEC4 - 1) idx = ROW_VEC4 - 1;   // tail clamp (unused data)
        float4 va = __ldg(&g4a[idx]);
        f0[4 * k + 0] = va.x; f0[4 * k + 1] = va.y;
        f0[4 * k + 2] = va.z; f0[4 * k + 3] = va.w;
    }
#pragma unroll
    for (int k = 0; k < 9; k++) {
        int idx = base + k;
        if (idx > ROW_VEC4 - 1) idx = ROW_VEC4 - 1;
        float4 vb = __ldg(&g4b[idx]);
        f1[4 * k + 0] = vb.x; f1[4 * k + 1] = vb.y;
        f1[4 * k + 2] = vb.z; f1[4 * k + 3] = vb.w;
    }

    // ---- AR(3) on wrapped first-diffs for both rows; each dx exactly once.
    float acc[3] = {0.f, 0.f, 0.f};
#pragma unroll
    for (int s = 0; s < 2; s++) {
        const float* f = (s == 0) ? f0 : f1;
#pragma unroll
        for (int d = 0; d < 3; d++) {
            float dx[CHUNK + 3];
#pragma unroll
            for (int j = 0; j < CHUNK + 3; j++)
                dx[j] = wrapf(f[3 * (j + 1) + d] - f[3 * j + d]);
            float ss = 0.f;
#pragma unroll
            for (int j = 0; j < CHUNK; j++) {
                float dyv = dx[j + 3] - (ph[d][0] * dx[j + 2]
                                       + ph[d][1] * dx[j + 1]
                                       + ph[d][2] * dx[j]);
                float u = dyv - cc[d];
                if (t0 + j < TPRIME) ss = fmaf(u, u, ss);
            }
            acc[d] += ss;
        }
    }

    // ---- Warp reduce, then 16-warp fold (both groups sum together: same m).
#pragma unroll
    for (int off = 16; off; off >>= 1)
#pragma unroll
        for (int d = 0; d < 3; d++)
            acc[d] += __shfl_xor_sync(0xffffffffu, acc[d], off);

    const int lane = tid & 31;
    const int warp = tid >> 5;
    if (lane == 0)
#pragma unroll
        for (int d = 0; d < 3; d++) sred[d][warp] = acc[d];
    __syncthreads();

    // ---- tid0 pushes this CTA's 3 sums into the LEADER CTA's slots via DSMEM.
    if (tid == 0) {
        float S[3];
#pragma unroll
        for (int d = 0; d < 3; d++) {
            float v = sred[d][0];
#pragma unroll
            for (int w = 1; w < NWARPS; w++) v += sred[d][w];
            S[d] = v;
        }
        uint32_t laddr = smem_u32(&slots[rank][0]);   // same layout in every CTA
        uint32_t raddr;
        asm volatile("mapa.shared::cluster.u32 %0, %1, %2;"
                     : "=r"(raddr) : "r"(laddr), "r"(0u));   // -> leader (rank 0)
#pragma unroll
        for (int d = 0; d < 3; d++)
            asm volatile("st.shared::cluster.f32 [%0], %1;"
                         :: "r"(raddr + 4u * d), "f"(S[d]) : "memory");
    }

    // Cluster barrier: release DSMEM stores, then leader may read.
    asm volatile("barrier.cluster.arrive.aligned;" ::: "memory");
    asm volatile("barrier.cluster.wait.aligned;" ::: "memory");

    // ---- Leader CTA: fold 4 ranks + closed-form winding constant, write out[m].
    //   sum_{k=-5..5} winding log-density collapses (sum k = 0, sum k^2 = 110)
    //   per (t,d) to: -5.5*u^2/var - 220*pi^2/var - 11*log(e) - 5.5*log(2*pi).
    // fp32 throughout: abs error ~1e4 vs tolerance budget ~8.5e7.
    if (rank == 0 && tid == 0) {
        float res = 0.f;
#pragma unroll
        for (int d = 0; d < 3; d++) {
            float Sd = 0.f;
#pragma unroll
            for (int r = 0; r < CLUSTER; r++) Sd += slots[r][d];
            float e   = fabsf(ar_eta[d]);            // scale = sqrt(eta^2)
            float var = e * e;
            float C = -220.f * (PI_F * PI_F) / var - 11.f * logf(e)
                      - 5.5f * logf(TWO_PI_F);
            res += -5.5f * Sd / var + (float)(N_SAMP * TPRIME) * C;
        }
        out[m] = res;
    }
}

extern "C" void kernel_launch(void* const* d_in, const int* in_sizes, int n_in,
                              void* d_out, int out_size) {
    const float* g      = (const float*)d_in[0];
    const float* ar_phi = (const float*)d_in[1];
    const float* ar_eta = (const float*)d_in[2];
    const float* ar_c   = (const float*)d_in[3];
    float* out = (float*)d_out;

    arp_cluster_kernel<<<GRID, BLOCK>>>(g, ar_phi, ar_eta, ar_c, out);
}